// round 6
// baseline (speedup 1.0000x reference)
#include <cuda_runtime.h>
#include <cuda_fp16.h>
#include <cstdint>

// ---------------- problem dims (fixed) ----------------
#define TOKENS (8*4096)   // B*L = 32768
#define DMODEL 256
#define DINNER 384
#define DSTATE 8
#define NXZ (3*DINNER)    // 1152

// ---------------- scratch (static device, no allocs) ----------------
__device__ __half g_xn[(size_t)TOKENS * DMODEL];    // layernorm out (fp16)
__device__ __half g_xz[(size_t)TOKENS * NXZ];       // silu(x_proj) | silu(z) | softplus(dt)
__device__ __half g_y [(size_t)TOKENS * DINNER];    // scan out (fp16)
__device__ __half g_wcat[(size_t)NXZ * DMODEL];     // [W_in(0:768); W_eff] fp16
__device__ __half g_wo[(size_t)DMODEL * DINNER];    // W_out fp16
__device__ __half g_wdh[(size_t)DINNER * DINNER];   // W_dt fp16
__device__ __half g_wt[(size_t)DMODEL * DINNER];    // W_in3 transposed fp16 [256][384]
__device__ float  g_bcat[NXZ];                      // [b_in(0:768); b_eff]
__device__ float  g_zeros[DMODEL];                  // zero bias (device globals zero-init)

// ---------------- helpers ----------------
__device__ __forceinline__ void mma_f16(float* d, const uint32_t* a, const uint32_t* b) {
    asm volatile(
        "mma.sync.aligned.m16n8k16.row.col.f32.f16.f16.f32 "
        "{%0,%1,%2,%3}, {%4,%5,%6,%7}, {%8,%9}, {%0,%1,%2,%3};\n"
        : "+f"(d[0]), "+f"(d[1]), "+f"(d[2]), "+f"(d[3])
        : "r"(a[0]), "r"(a[1]), "r"(a[2]), "r"(a[3]),
          "r"(b[0]), "r"(b[1]));
}
__device__ __forceinline__ void cp_async16(void* smem_dst, const void* gmem_src) {
    uint32_t dst = (uint32_t)__cvta_generic_to_shared(smem_dst);
    asm volatile("cp.async.cg.shared.global [%0], [%1], 16;" :: "r"(dst), "l"(gmem_src));
}

// ---------------- prep: fp32->fp16 conversions + bias copy (one kernel) ----------------
// quad regions: [0,49152): W_in rows 0..768 -> wcat ; [49152,73728): W_out -> wo ;
// [73728,110592): W_dt -> wdh ; [110592,110784): b_in 0..768 -> bcat (float copy)
__global__ __launch_bounds__(256)
void prep_cvt(const float* __restrict__ W_in, const float* __restrict__ W_out,
              const float* __restrict__ W_dt, const float* __restrict__ b_in,
              __half* __restrict__ wcat, __half* __restrict__ wo,
              __half* __restrict__ wdh, float* __restrict__ bcat) {
    int q = blockIdx.x * 256 + threadIdx.x;
    const float* src; __half* dst; int base;
    if (q < 49152)        { src = W_in;  dst = wcat; base = q; }
    else if (q < 73728)   { src = W_out; dst = wo;   base = q - 49152; }
    else if (q < 110592)  { src = W_dt;  dst = wdh;  base = q - 73728; }
    else if (q < 110784)  {
        int i = (q - 110592) * 4;
        *reinterpret_cast<float4*>(&bcat[i]) = *reinterpret_cast<const float4*>(&b_in[i]);
        return;
    } else return;
    int i = base * 4;
    float4 v = *reinterpret_cast<const float4*>(&src[i]);
    *reinterpret_cast<__half2*>(&dst[i])     = __floats2half2_rn(v.x, v.y);
    *reinterpret_cast<__half2*>(&dst[i + 2]) = __floats2half2_rn(v.z, v.w);
}

// ---------------- transpose W_in3 [384][256] -> wt fp16 [256][384] ----------------
__global__ __launch_bounds__(1024)
void trans_kernel(const float* __restrict__ W_in, __half* __restrict__ wt) {
    __shared__ float tile[32][33];
    int j0 = blockIdx.x * 32, m0 = blockIdx.y * 32;
    int tx = threadIdx.x & 31, ty = threadIdx.x >> 5;
    tile[ty][tx] = W_in[(size_t)(768 + j0 + ty) * DMODEL + m0 + tx];
    __syncthreads();
    wt[(size_t)(m0 + ty) * DINNER + j0 + tx] = __float2half(tile[tx][ty]);
}

// ---------------- b_eff[i] = b_dt[i] + sum_j W_dt[i][j] * b_in[768+j] ----------------
__global__ __launch_bounds__(384)
void beff_kernel(const float* __restrict__ W_dt, const float* __restrict__ b_dt,
                 const float* __restrict__ b_in, float* __restrict__ bcat) {
    int i = threadIdx.x;
    float acc = b_dt[i];
    for (int j = 0; j < DINNER; j++)
        acc = fmaf(W_dt[(size_t)i * DINNER + j], b_in[768 + j], acc);
    bcat[768 + i] = acc;
}

// ---------------- LayerNorm: one warp per token, fp16 out ----------------
__global__ __launch_bounds__(256)
void ln_kernel(const float* __restrict__ x, const float* __restrict__ gamma,
               const float* __restrict__ beta, __half* __restrict__ out) {
    int warp = threadIdx.x >> 5;
    int lane = threadIdx.x & 31;
    size_t tok = (size_t)blockIdx.x * 8 + warp;
    const float* xr = x + tok * DMODEL;
    int k = lane * 8;
    float4 v0 = *reinterpret_cast<const float4*>(xr + k);
    float4 v1 = *reinterpret_cast<const float4*>(xr + k + 4);
    float s = v0.x + v0.y + v0.z + v0.w + v1.x + v1.y + v1.z + v1.w;
    float q = v0.x*v0.x + v0.y*v0.y + v0.z*v0.z + v0.w*v0.w
            + v1.x*v1.x + v1.y*v1.y + v1.z*v1.z + v1.w*v1.w;
    #pragma unroll
    for (int off = 16; off; off >>= 1) {
        s += __shfl_xor_sync(0xffffffffu, s, off);
        q += __shfl_xor_sync(0xffffffffu, q, off);
    }
    float mu   = s * (1.0f / DMODEL);
    float var  = q * (1.0f / DMODEL) - mu * mu;
    float rstd = rsqrtf(var + 1e-5f);
    float4 g0 = *reinterpret_cast<const float4*>(gamma + k);
    float4 g1 = *reinterpret_cast<const float4*>(gamma + k + 4);
    float4 bb0 = *reinterpret_cast<const float4*>(beta + k);
    float4 bb1 = *reinterpret_cast<const float4*>(beta + k + 4);
    __half2 h[4];
    h[0] = __floats2half2_rn((v0.x-mu)*rstd*g0.x+bb0.x, (v0.y-mu)*rstd*g0.y+bb0.y);
    h[1] = __floats2half2_rn((v0.z-mu)*rstd*g0.z+bb0.z, (v0.w-mu)*rstd*g0.w+bb0.w);
    h[2] = __floats2half2_rn((v1.x-mu)*rstd*g1.x+bb1.x, (v1.y-mu)*rstd*g1.y+bb1.y);
    h[3] = __floats2half2_rn((v1.z-mu)*rstd*g1.z+bb1.z, (v1.w-mu)*rstd*g1.w+bb1.w);
    *reinterpret_cast<uint4*>(out + tok * DMODEL + k) = *reinterpret_cast<uint4*>(h);
}

// ============ fp16 GEMM: C[M,N] = epi(A[M,K] @ W[N,K]^T + bias) ============
// BM=128 BN=128 BK=32(halves), 256 threads, warps 2(M)x4(N), warp tile 64x32.
// 3-stage cp.async ring. Padded smem rows (40 halves) -> conflict-free LDS.32.
// EPI: 0 = fused: silu if bn<768 else softplus (half out)
//      2 = +residual (float out)
//      3 = plain bias (half out)  [used for W_eff precompute]
#define BM 128
#define BN 128
#define BK 32
#define BKP 40
#define NSTAGE 3
#define STAGE_H ((BM + BN) * BKP)
#define GEMM_SMEM (NSTAGE * STAGE_H * 2)

template<int EPI>
__global__ __launch_bounds__(256, 2)
void gemm_f16(const __half* __restrict__ A, int lda, int aoff,
              const __half* __restrict__ W, int K,
              const float* __restrict__ bias,
              void* __restrict__ Cv, int ldc,
              const float* __restrict__ resid) {
    extern __shared__ __half smh[];

    int tid = threadIdx.x;
    int wid = tid >> 5, lane = tid & 31;
    int warp_m = wid & 1;
    int warp_n = wid >> 1;
    int bm = blockIdx.y * BM;
    int bn = blockIdx.x * BN;

    const __half* Ap = A + (size_t)bm * lda + aoff;
    const __half* Wp = W + (size_t)bn * K;
    int nk = K / BK;

    auto stage = [&](int s, int kc) {
        __half* sA = smh + s * STAGE_H;
        __half* sB = sA + BM * BKP;
        #pragma unroll
        for (int i = 0; i < 2; i++) {
            int j = tid + i * 256;
            int row = j >> 2, c = j & 3;
            cp_async16(sA + row * BKP + c * 8, Ap + (size_t)row * lda + kc + c * 8);
        }
        #pragma unroll
        for (int i = 0; i < 2; i++) {
            int j = tid + i * 256;
            int row = j >> 2, c = j & 3;
            cp_async16(sB + row * BKP + c * 8, Wp + (size_t)row * K + kc + c * 8);
        }
        asm volatile("cp.async.commit_group;" ::: "memory");
    };

    #pragma unroll
    for (int s = 0; s < NSTAGE; s++) stage(s, s * BK);

    float acc[4][4][4] = {};
    int g = lane >> 2, c2 = (lane & 3) * 2;

    for (int kt = 0; kt < nk; kt++) {
        int buf = kt % NSTAGE;
        int rem = nk - 1 - kt;
        if (rem >= 2)      asm volatile("cp.async.wait_group 2;" ::: "memory");
        else if (rem == 1) asm volatile("cp.async.wait_group 1;" ::: "memory");
        else               asm volatile("cp.async.wait_group 0;" ::: "memory");
        __syncthreads();

        const __half* as = smh + buf * STAGE_H + (warp_m * 64 + g) * BKP;
        const __half* bs = smh + buf * STAGE_H + BM * BKP + (warp_n * 32 + g) * BKP;
        #pragma unroll
        for (int k16 = 0; k16 < BK / 16; k16++) {
            int kb = k16 * 16 + c2;
            uint32_t afr[4][4], bfr[4][2];
            #pragma unroll
            for (int mt = 0; mt < 4; mt++) {
                const __half* ap = as + mt * 16 * BKP;
                afr[mt][0] = *reinterpret_cast<const uint32_t*>(&ap[kb]);
                afr[mt][1] = *reinterpret_cast<const uint32_t*>(&ap[8 * BKP + kb]);
                afr[mt][2] = *reinterpret_cast<const uint32_t*>(&ap[kb + 8]);
                afr[mt][3] = *reinterpret_cast<const uint32_t*>(&ap[8 * BKP + kb + 8]);
            }
            #pragma unroll
            for (int nt = 0; nt < 4; nt++) {
                const __half* bp = bs + nt * 8 * BKP;
                bfr[nt][0] = *reinterpret_cast<const uint32_t*>(&bp[kb]);
                bfr[nt][1] = *reinterpret_cast<const uint32_t*>(&bp[kb + 8]);
            }
            #pragma unroll
            for (int mt = 0; mt < 4; mt++)
                #pragma unroll
                for (int nt = 0; nt < 4; nt++)
                    mma_f16(acc[mt][nt], afr[mt], bfr[nt]);
        }
        __syncthreads();
        if (kt + NSTAGE < nk) stage(buf, (kt + NSTAGE) * BK);
    }

    // ---------------- epilogue ----------------
    bool do_silu = (EPI == 0) && (bn < 2 * DINNER);
    #pragma unroll
    for (int mt = 0; mt < 4; mt++) {
        #pragma unroll
        for (int nt = 0; nt < 4; nt++) {
            int row = bm + warp_m * 64 + mt * 16 + g;
            int col = bn + warp_n * 32 + nt * 8 + c2;
            float bv0 = bias[col], bv1 = bias[col + 1];
            float v[4];
            v[0] = acc[mt][nt][0] + bv0; v[1] = acc[mt][nt][1] + bv1;
            v[2] = acc[mt][nt][2] + bv0; v[3] = acc[mt][nt][3] + bv1;
            if (EPI == 0) {
                if (do_silu) {
                    #pragma unroll
                    for (int i = 0; i < 4; i++) v[i] = v[i] / (1.0f + __expf(-v[i]));
                } else {
                    #pragma unroll
                    for (int i = 0; i < 4; i++)
                        v[i] = fmaxf(v[i], 0.0f) + log1pf(__expf(-fabsf(v[i])));
                }
            }
            if (EPI != 2) {
                __half* C = (__half*)Cv;
                *reinterpret_cast<__half2*>(&C[(size_t)row * ldc + col])
                    = __floats2half2_rn(v[0], v[1]);
                *reinterpret_cast<__half2*>(&C[(size_t)(row + 8) * ldc + col])
                    = __floats2half2_rn(v[2], v[3]);
            } else {
                float* C = (float*)Cv;
                float2 r0 = *reinterpret_cast<const float2*>(&resid[(size_t)row * ldc + col]);
                float2 r1 = *reinterpret_cast<const float2*>(&resid[(size_t)(row + 8) * ldc + col]);
                *reinterpret_cast<float2*>(&C[(size_t)row * ldc + col])
                    = make_float2(v[0] + r0.x, v[1] + r0.y);
                *reinterpret_cast<float2*>(&C[(size_t)(row + 8) * ldc + col])
                    = make_float2(v[2] + r1.x, v[3] + r1.y);
            }
        }
    }
}

// ---------------- chunked scan + gating (fp16 I/O; dt lives in xz cols 768..) ----------------
__global__ __launch_bounds__(128)
void scan_kernel(const __half* __restrict__ xz,
                 const float* __restrict__ A_log, const float* __restrict__ Dvec,
                 __half* __restrict__ y) {
    int di = blockIdx.x * 128 + threadIdx.x;           // 0..383
    size_t tok0 = (size_t)blockIdx.y * 32;             // chunk base token
    float nA[DSTATE];
    #pragma unroll
    for (int s = 0; s < DSTATE; s++)
        nA[s] = -__expf(A_log[di * DSTATE + s]);
    float Dv = Dvec[di];
    float h[DSTATE] = {};
    #pragma unroll 4
    for (int t = 0; t < 32; t++) {
        size_t tok = tok0 + t;
        float xp  = __half2float(xz[tok * NXZ + di]);
        float zv  = __half2float(xz[tok * NXZ + DINNER + di]);
        float dtv = __half2float(xz[tok * NXZ + 2 * DINNER + di]);
        float ys = 0.0f;
        #pragma unroll
        for (int s = 0; s < DSTATE; s++) {
            h[s] = fmaf(h[s], __expf(dtv * nA[s]), xp);
            ys += h[s];
        }
        y[tok * DINNER + di] = __float2half(fmaf(ys, zv, xp * Dv));
    }
}

// ---------------- launch ----------------
extern "C" void kernel_launch(void* const* d_in, const int* in_sizes, int n_in,
                              void* d_out, int out_size) {
    (void)in_sizes; (void)n_in; (void)out_size;
    const float* x     = (const float*)d_in[0];
    const float* gamma = (const float*)d_in[1];
    const float* beta  = (const float*)d_in[2];
    const float* W_in  = (const float*)d_in[3];
    const float* b_in  = (const float*)d_in[4];
    const float* W_dt  = (const float*)d_in[5];
    const float* b_dt  = (const float*)d_in[6];
    const float* A_log = (const float*)d_in[7];
    const float* D_vec = (const float*)d_in[8];
    const float* W_out = (const float*)d_in[9];
    const float* b_out = (const float*)d_in[10];
    float* out = (float*)d_out;

    __half *xn, *xz, *y, *wcat, *wo, *wdh, *wt;
    float *bcat, *zeros;
    cudaGetSymbolAddress((void**)&xn, g_xn);
    cudaGetSymbolAddress((void**)&xz, g_xz);
    cudaGetSymbolAddress((void**)&y,  g_y);
    cudaGetSymbolAddress((void**)&wcat, g_wcat);
    cudaGetSymbolAddress((void**)&wo, g_wo);
    cudaGetSymbolAddress((void**)&wdh, g_wdh);
    cudaGetSymbolAddress((void**)&wt, g_wt);
    cudaGetSymbolAddress((void**)&bcat, g_bcat);
    cudaGetSymbolAddress((void**)&zeros, g_zeros);

    cudaFuncSetAttribute(gemm_f16<0>, cudaFuncAttributeMaxDynamicSharedMemorySize, GEMM_SMEM);
    cudaFuncSetAttribute(gemm_f16<2>, cudaFuncAttributeMaxDynamicSharedMemorySize, GEMM_SMEM);
    cudaFuncSetAttribute(gemm_f16<3>, cudaFuncAttributeMaxDynamicSharedMemorySize, GEMM_SMEM);

    // 0) prep: conversions + transpose + b_eff + W_eff = W_dt @ W_in3
    prep_cvt<<<433, 256>>>(W_in, W_out, W_dt, b_in, wcat, wo, wdh, bcat);
    trans_kernel<<<dim3(DINNER / 32, DMODEL / 32), 1024>>>(W_in, wt);
    beff_kernel<<<1, 384>>>(W_dt, b_dt, b_in, bcat);
    // W_eff[384][256] = wdh[384][384] @ wt[256][384]^T -> wcat rows 768..1152
    gemm_f16<3><<<dim3(DMODEL / BN, DINNER / BM), 256, GEMM_SMEM>>>(
        wdh, DINNER, 0, wt, DINNER, zeros, wcat + (size_t)768 * DMODEL, DMODEL, nullptr);

    // 1) layernorm (fp16 out)
    ln_kernel<<<TOKENS / 8, 256>>>(x, gamma, beta, xn);

    // 2) fused xz|dt = epi(xn @ Wcat^T + bcat): silu cols<768, softplus cols>=768
    gemm_f16<0><<<dim3(NXZ / BN, TOKENS / BM), 256, GEMM_SMEM>>>(
        xn, DMODEL, 0, wcat, DMODEL, bcat, xz, NXZ, nullptr);

    // 3) chunked SSM scan + gating
    scan_kernel<<<dim3(DINNER / 128, TOKENS / 32), 128>>>(xz, A_log, D_vec, y);

    // 4) out = y @ W_out^T + b_out + residual
    gemm_f16<2><<<dim3(DMODEL / BN, TOKENS / BM), 256, GEMM_SMEM>>>(
        y, DINNER, 0, wo, DINNER, b_out, out, DMODEL, x);
}